// round 5
// baseline (speedup 1.0000x reference)
#include <cuda_runtime.h>
#include <cuda_bf16.h>
#include <cstdint>

// Problem constants (fixed shapes)
#define NB      128                 // graphs
#define NPG     1000                // nodes per graph
#define NN      (NB * NPG)          // 128000 nodes
#define EPG     16000
#define NEDGE   (NB * EPG)          // 2048000 edges
#define DD      128                 // feature dim
#define CC      10                  // classes
// K=64 appears only as the 1/K pooling factor: softmax rows sum to 1, so the
// assignment GCN + softmax + S^T A S (Ap) are provably dead for the output.

typedef unsigned long long ull;

// ---------------- scratch (static device globals; no allocation) -------------
__device__ int   g_deg[NN];
__device__ int   g_rowstart[NN + 1];
__device__ int   g_cursor[NN];
__device__ int   g_bsum[128];
__device__ int   g_esrc[NEDGE];
__device__ float g_dinv[NN];
__device__ float g_y[(size_t)NN * DD];
__device__ float g_h[(size_t)NN * DD];
__device__ float g_pooled[NB * DD];

// ---------------- f32x2 packed-FMA helpers (sm_100+) -------------------------
__device__ __forceinline__ ull pack2(float x, float y) {
    ull r; asm("mov.b64 %0, {%1, %2};" : "=l"(r) : "f"(x), "f"(y)); return r;
}
__device__ __forceinline__ void fma2(ull& d, ull a, ull b) {
    asm("fma.rn.f32x2 %0, %1, %2, %0;" : "+l"(d) : "l"(a), "l"(b));
}
__device__ __forceinline__ float2 unpack2(ull v) {
    float2 f; asm("mov.b64 {%0, %1}, %2;" : "=f"(f.x), "=f"(f.y) : "l"(v)); return f;
}

// ---------------- CSR build ---------------------------------------------------
__global__ void k_zero_deg(int* __restrict__ deg) {
    deg[blockIdx.x * 1024 + threadIdx.x] = 0;
}

__global__ void k_count(const int* __restrict__ dst, int* __restrict__ deg) {
    int e = blockIdx.x * 1024 + threadIdx.x;
    atomicAdd(&deg[dst[e]], 1);
}

__global__ void __launch_bounds__(1024) k_scanA(const int* __restrict__ deg,
                                                int* __restrict__ rowstart,
                                                int* __restrict__ bsum) {
    int tid = threadIdx.x;
    int i = blockIdx.x * 1024 + tid;
    int v = deg[i];
    int lane = tid & 31, warp = tid >> 5;
    int incl = v;
#pragma unroll
    for (int d = 1; d < 32; d <<= 1) {
        int t = __shfl_up_sync(0xffffffffu, incl, d);
        if (lane >= d) incl += t;
    }
    __shared__ int ws[32];
    if (lane == 31) ws[warp] = incl;
    __syncthreads();
    if (warp == 0) {
        int w = ws[lane];
#pragma unroll
        for (int d = 1; d < 32; d <<= 1) {
            int t = __shfl_up_sync(0xffffffffu, w, d);
            if (lane >= d) w += t;
        }
        ws[lane] = w;
    }
    __syncthreads();
    int off = (warp == 0) ? 0 : ws[warp - 1];
    incl += off;
    rowstart[i] = incl - v;          // exclusive within block
    if (tid == 1023) bsum[blockIdx.x] = incl;
}

__global__ void k_scanB(int* __restrict__ bsum) {
    int tid = threadIdx.x;                    // 128 threads, 125 valid
    int v = (tid < 125) ? bsum[tid] : 0;
    int lane = tid & 31, warp = tid >> 5;
    int incl = v;
#pragma unroll
    for (int d = 1; d < 32; d <<= 1) {
        int t = __shfl_up_sync(0xffffffffu, incl, d);
        if (lane >= d) incl += t;
    }
    __shared__ int ws[4];
    if (lane == 31) ws[warp] = incl;
    __syncthreads();
    int off = 0;
    if (warp >= 1) off += ws[0];
    if (warp >= 2) off += ws[1];
    if (warp >= 3) off += ws[2];
    incl += off;
    if (tid < 125) bsum[tid] = incl - v;      // exclusive block offsets
}

__global__ void k_scanC(int* __restrict__ rowstart, const int* __restrict__ bsum,
                        const int* __restrict__ deg, int* __restrict__ cursor,
                        float* __restrict__ dinv) {
    int tid = threadIdx.x;
    int i = blockIdx.x * 1024 + tid;
    int rs = rowstart[i] + bsum[blockIdx.x];
    rowstart[i] = rs;
    cursor[i] = rs;
    dinv[i] = rsqrtf((float)deg[i] + 1.0f);   // +1 self-loop
    if (i == 0) rowstart[NN] = NEDGE;
}

__global__ void k_scatter(const int* __restrict__ src, const int* __restrict__ dst,
                          int* __restrict__ cursor, int* __restrict__ esrc) {
    int e = blockIdx.x * 1024 + threadIdx.x;
    int d = dst[e];
    int pos = atomicAdd(&cursor[d], 1);
    esrc[pos] = src[e];
}

// ---------------- GEMM: Y[n,:] = (A[n,:] @ W) * dinv[n] ----------------------
// 128 rows x 128 cols per block, 256 threads, 8x8 microtile via f32x2 FMAs.
// A-tile staged k-major with stride 130 (pad kills the 4KB aliasing of the two
// half-k writers). Microtile columns are STRIDED (col = 2*cg + 32*j) so each
// W LDS.64 reads 16 contiguous ulls (128B, conflict-free) instead of the
// 4-way-conflicted cg*8 pattern. Global A loads software-pipelined.
#define ASTRIDE 130
#define GEMM_SMEM ((16 * ASTRIDE + 128 * 128) * 4)

__global__ void __launch_bounds__(256) k_gemm_scale(const float* __restrict__ A,
                                                    const float* __restrict__ W,
                                                    const float* __restrict__ dinv,
                                                    float* __restrict__ Y) {
    extern __shared__ float smem[];
    float* As = smem;                    // [16][ASTRIDE] (k-major, padded)
    float* Ws = smem + 16 * ASTRIDE;     // [128][128]    (k, then col)

    int tid = threadIdx.x;
    {   // load full W (16384 floats) via float4
        const float4* W4 = (const float4*)W;
        float4* Ws4 = (float4*)Ws;
#pragma unroll
        for (int i = 0; i < 16; i++) Ws4[tid + 256 * i] = W4[tid + 256 * i];
    }

    int cg = tid & 15;    // col lane: covers col pairs {2cg+32j, 2cg+32j+1}, j=0..3
    int rg = tid >> 4;    // row group: rows rg*8 .. rg*8+7
    int row0 = blockIdx.x * 128;

    // A-load role: thread covers row r, k-half kh..kh+7
    int lr = tid >> 1;
    int lkh = (tid & 1) * 8;
    const float* aptr = A + (size_t)(row0 + lr) * DD + lkh;

    ull acc[8][4];
#pragma unroll
    for (int i = 0; i < 8; i++)
#pragma unroll
        for (int j = 0; j < 4; j++) acc[i][j] = 0ull;

    // prefetch chunk 0
    float4 p0 = *(const float4*)(aptr);
    float4 p1 = *(const float4*)(aptr + 4);

#pragma unroll 1
    for (int kc = 0; kc < 128; kc += 16) {
        __syncthreads();
        {   // store staged chunk (k-major, padded stride)
            float* s = As + lkh * ASTRIDE + lr;
            s[0 * ASTRIDE] = p0.x; s[1 * ASTRIDE] = p0.y;
            s[2 * ASTRIDE] = p0.z; s[3 * ASTRIDE] = p0.w;
            s[4 * ASTRIDE] = p1.x; s[5 * ASTRIDE] = p1.y;
            s[6 * ASTRIDE] = p1.z; s[7 * ASTRIDE] = p1.w;
        }
        __syncthreads();
        if (kc + 16 < 128) {   // prefetch next chunk during compute
            p0 = *(const float4*)(aptr + kc + 16);
            p1 = *(const float4*)(aptr + kc + 16 + 4);
        }
#pragma unroll
        for (int k = 0; k < 16; k++) {
            const float* arow = As + k * ASTRIDE + rg * 8;
            float2 a01 = *(const float2*)(arow + 0);
            float2 a23 = *(const float2*)(arow + 2);
            float2 a45 = *(const float2*)(arow + 4);
            float2 a67 = *(const float2*)(arow + 6);
            ull av[8];
            av[0] = pack2(a01.x, a01.x); av[1] = pack2(a01.y, a01.y);
            av[2] = pack2(a23.x, a23.x); av[3] = pack2(a23.y, a23.y);
            av[4] = pack2(a45.x, a45.x); av[5] = pack2(a45.y, a45.y);
            av[6] = pack2(a67.x, a67.x); av[7] = pack2(a67.y, a67.y);
            const ull* wk = (const ull*)(Ws + (kc + k) * 128);   // 64 ulls/row
            ull bv0 = wk[cg + 0];    // float cols 2cg+0,1    (lanes contiguous)
            ull bv1 = wk[cg + 16];   // float cols 2cg+32,33
            ull bv2 = wk[cg + 32];   // float cols 2cg+64,65
            ull bv3 = wk[cg + 48];   // float cols 2cg+96,97
#pragma unroll
            for (int i = 0; i < 8; i++) {
                fma2(acc[i][0], av[i], bv0);
                fma2(acc[i][1], av[i], bv1);
                fma2(acc[i][2], av[i], bv2);
                fma2(acc[i][3], av[i], bv3);
            }
        }
    }

#pragma unroll
    for (int i = 0; i < 8; i++) {
        int r = row0 + rg * 8 + i;
        float dv = dinv[r];
        float* yrow = Y + (size_t)r * DD + cg * 2;
#pragma unroll
        for (int j = 0; j < 4; j++) {
            float2 f = unpack2(acc[i][j]);
            float2 o = make_float2(f.x * dv, f.y * dv);
            *(float2*)(yrow + j * 32) = o;      // lanes write contiguous 128B
        }
    }
}

// ---------------- aggregation (SMEM-staged, per-graph) ------------------------
// out[i,:] = relu(dinv[i]*(sum_{s->i} y[s,:] + y[i,:]) + bias)
// Grid: (NB graphs, 4 dim-quarters). Each CTA stages its graph's 1000x32-float
// slice of y into SMEM (128 KB), then warp-per-dst-node gathers from SMEM
// (conflict-free: lane = dim word). Edge rows stream from the smem crossbar at
// ~1 row/cyc/SM instead of sharing the chip-wide L2 pipe.
#define AGG_SMEM (NPG * 32 * 4)   // 128000 B

__global__ void __launch_bounds__(256) k_agg(const float* __restrict__ y,
                                             const float* __restrict__ dinv,
                                             const int* __restrict__ rowstart,
                                             const int* __restrict__ esrc,
                                             const float* __restrict__ bias,
                                             float* __restrict__ out) {
    extern __shared__ float sy[];          // [NPG][32]
    int g = blockIdx.x;
    int q = blockIdx.y;                    // dim quarter: cols q*32 .. q*32+31
    int base = g * NPG;
    int tid = threadIdx.x;
    int lane = tid & 31;
    int warp = tid >> 5;                   // 8 warps

    // stage: sy[n][0..31] = y[base+n][q*32 .. q*32+31]
    {
        const float4* yv4 = (const float4*)y;   // row = 32 float4
        float4* s4 = (float4*)sy;
        for (int idx = tid; idx < NPG * 8; idx += 256) {
            int n = idx >> 3;
            int f = idx & 7;
            s4[idx] = yv4[(size_t)(base + n) * 32 + q * 8 + f];
        }
    }
    __syncthreads();

    float bb = bias[q * 32 + lane];

    for (int il = warp; il < NPG; il += 8) {
        int node = base + il;
        int s0 = rowstart[node];
        int s1 = rowstart[node + 1];

        float sum = sy[il * 32 + lane];    // self-loop (already dinv-scaled)

        for (int j = s0; j < s1; j += 32) {
            int cnt = s1 - j; if (cnt > 32) cnt = 32;
            int rel = 0;
            if (lane < cnt) rel = esrc[j + lane] - base;   // in [0,NPG)
            int t = 0;
            for (; t + 4 <= cnt; t += 4) {
                int r0 = __shfl_sync(0xffffffffu, rel, t + 0);
                int r1 = __shfl_sync(0xffffffffu, rel, t + 1);
                int r2 = __shfl_sync(0xffffffffu, rel, t + 2);
                int r3 = __shfl_sync(0xffffffffu, rel, t + 3);
                float v0 = sy[r0 * 32 + lane];
                float v1 = sy[r1 * 32 + lane];
                float v2 = sy[r2 * 32 + lane];
                float v3 = sy[r3 * 32 + lane];
                sum += (v0 + v1) + (v2 + v3);
            }
            for (; t < cnt; t++) {
                int r0 = __shfl_sync(0xffffffffu, rel, t);
                sum += sy[r0 * 32 + lane];
            }
        }

        float dv = dinv[node];
        out[(size_t)node * DD + q * 32 + lane] = fmaxf(fmaf(dv, sum, bb), 0.0f);
    }
}

// ---------------- pooling: pooled[b,d] = (1/64) * sum_n NE[b,n,d] -------------
__global__ void __launch_bounds__(128) k_pool(const float* __restrict__ ne,
                                              float* __restrict__ pooled) {
    int b = blockIdx.x;
    int tid = threadIdx.x;
    const float* p = ne + (size_t)b * NPG * DD + tid;
    float s = 0.0f;
#pragma unroll 4
    for (int n = 0; n < NPG; n++) s += p[(size_t)n * DD];
    pooled[b * DD + tid] = s * (1.0f / 64.0f);
}

// ---------------- final MLP ----------------------------------------------------
__global__ void __launch_bounds__(128) k_mlp(const float* __restrict__ pooled,
                                             const float* __restrict__ W1,
                                             const float* __restrict__ b1,
                                             const float* __restrict__ W2,
                                             const float* __restrict__ b2,
                                             float* __restrict__ out) {
    int b = blockIdx.x;
    int tid = threadIdx.x;
    __shared__ float p[DD], t1[DD];
    p[tid] = pooled[b * DD + tid];
    __syncthreads();
    float s = b1[tid];
#pragma unroll 8
    for (int d = 0; d < DD; d++) s = fmaf(p[d], W1[d * DD + tid], s);
    t1[tid] = fmaxf(s, 0.0f);
    __syncthreads();
    if (tid < CC) {
        float o = b2[tid];
#pragma unroll 8
        for (int j = 0; j < DD; j++) o = fmaf(t1[j], W2[j * CC + tid], o);
        out[b * CC + tid] = o;
    }
}

// ---------------- launch --------------------------------------------------------
extern "C" void kernel_launch(void* const* d_in, const int* in_sizes, int n_in,
                              void* d_out, int out_size) {
    (void)in_sizes; (void)n_in; (void)out_size;
    const float* x     = (const float*)d_in[0];
    const int*   ei    = (const int*)d_in[1];
    const int*   src   = ei;
    const int*   dst   = ei + NEDGE;
    const float* W_pre = (const float*)d_in[3];
    const float* b_pre = (const float*)d_in[4];
    const float* W_emb = (const float*)d_in[5];
    const float* b_emb = (const float*)d_in[6];
    // d_in[7], d_in[8]: W_asn/b_asn -- dead (softmax rows sum to 1)
    const float* W1    = (const float*)d_in[9];
    const float* b1    = (const float*)d_in[10];
    const float* W2    = (const float*)d_in[11];
    const float* b2    = (const float*)d_in[12];
    float* out = (float*)d_out;

    int *deg, *rowstart, *cursor, *bsum, *esrc;
    float *dinv, *y, *h, *pooled;
    cudaGetSymbolAddress((void**)&deg, g_deg);
    cudaGetSymbolAddress((void**)&rowstart, g_rowstart);
    cudaGetSymbolAddress((void**)&cursor, g_cursor);
    cudaGetSymbolAddress((void**)&bsum, g_bsum);
    cudaGetSymbolAddress((void**)&esrc, g_esrc);
    cudaGetSymbolAddress((void**)&dinv, g_dinv);
    cudaGetSymbolAddress((void**)&y, g_y);
    cudaGetSymbolAddress((void**)&h, g_h);
    cudaGetSymbolAddress((void**)&pooled, g_pooled);

    cudaFuncSetAttribute(k_gemm_scale, cudaFuncAttributeMaxDynamicSharedMemorySize,
                         GEMM_SMEM);
    cudaFuncSetAttribute(k_agg, cudaFuncAttributeMaxDynamicSharedMemorySize,
                         AGG_SMEM);

    // CSR build (per launch; deterministic work)
    k_zero_deg<<<NN / 1024, 1024>>>(deg);
    k_count<<<NEDGE / 1024, 1024>>>(dst, deg);
    k_scanA<<<NN / 1024, 1024>>>(deg, rowstart, bsum);
    k_scanB<<<1, 128>>>(bsum);
    k_scanC<<<NN / 1024, 1024>>>(rowstart, bsum, deg, cursor, dinv);
    k_scatter<<<NEDGE / 1024, 1024>>>(src, dst, cursor, esrc);

    dim3 agrid(NB, 4);

    // layer 1: h = relu(Ahat @ (x W_pre) + b_pre)
    k_gemm_scale<<<NN / 128, 256, GEMM_SMEM>>>(x, W_pre, dinv, y);
    k_agg<<<agrid, 256, AGG_SMEM>>>(y, dinv, rowstart, esrc, b_pre, h);

    // layer 2: NE = relu(Ahat @ (h W_emb) + b_emb)   (y buffer reused)
    k_gemm_scale<<<NN / 128, 256, GEMM_SMEM>>>(h, W_emb, dinv, y);
    k_agg<<<agrid, 256, AGG_SMEM>>>(y, dinv, rowstart, esrc, b_emb, h);

    // pooled mean over clusters == (1/K) * per-graph node sum of NE
    k_pool<<<NB, 128>>>(h, pooled);
    k_mlp<<<NB, 128>>>(pooled, W1, b1, W2, b2, out);
}